// round 8
// baseline (speedup 1.0000x reference)
#include <cuda_runtime.h>
#include <cuda_bf16.h>
#include <math.h>

#define TS   512
#define NB   32
#define DIN  512
#define HID  1024
#define G2   2048

// ---------------- global scratch ----------------
__device__ float g_XG[(size_t)TS * NB * G2];
__device__ float g_XC[(size_t)TS * NB * HID];
__device__ float g_h [NB * HID];
__device__ float g_rh[NB * HID];
__device__ float g_u [NB * HID];
__device__ unsigned int g_barg[8 * 64];

__global__ void gru_init_kernel() {
    int idx = blockIdx.x * blockDim.x + threadIdx.x;
    if (idx < NB * HID) g_h[idx] = 0.0f;
    if (idx < 8 * 64) g_barg[idx] = 0u;
}

// ---------------- precompute GEMM (unchanged) ----------------
#define BM 128
#define BN 64
#define BK 16
#define APAD 132

__global__ void __launch_bounds__(256) sgemm_bias_kernel(
    const float* __restrict__ A, const float* __restrict__ W,
    const float* __restrict__ bias, float* __restrict__ C,
    int M, int N, int K, int ldw)
{
    __shared__ float As[BK * APAD];
    __shared__ float Ws[BK * BN];

    const int tid = threadIdx.x;
    const int tx = tid & 15;
    const int ty = tid >> 4;
    const int m0 = blockIdx.y * BM;
    const int n0 = blockIdx.x * BN;

    float acc[8][4];
#pragma unroll
    for (int i = 0; i < 8; ++i)
#pragma unroll
        for (int j = 0; j < 4; ++j) acc[i][j] = 0.0f;

    for (int k0 = 0; k0 < K; k0 += BK) {
        {
            const int kq = tid & 3;
            const int mr = tid >> 2;
#pragma unroll
            for (int it = 0; it < 2; ++it) {
                int m = mr + it * 64;
                float4 v = *(const float4*)&A[(size_t)(m0 + m) * K + k0 + kq * 4];
                As[(kq * 4 + 0) * APAD + m] = v.x;
                As[(kq * 4 + 1) * APAD + m] = v.y;
                As[(kq * 4 + 2) * APAD + m] = v.z;
                As[(kq * 4 + 3) * APAD + m] = v.w;
            }
        }
        {
            const int nq = tid & 15;
            const int kr = tid >> 4;
            float4 v = *(const float4*)&W[(size_t)(k0 + kr) * ldw + n0 + nq * 4];
            *(float4*)&Ws[kr * BN + nq * 4] = v;
        }
        __syncthreads();
#pragma unroll
        for (int kk = 0; kk < BK; ++kk) {
            float4 w4 = *(const float4*)&Ws[kk * BN + tx * 4];
            float4 a0 = *(const float4*)&As[kk * APAD + ty * 8];
            float4 a1 = *(const float4*)&As[kk * APAD + ty * 8 + 4];
            float a[8];
            a[0] = a0.x; a[1] = a0.y; a[2] = a0.z; a[3] = a0.w;
            a[4] = a1.x; a[5] = a1.y; a[6] = a1.z; a[7] = a1.w;
#pragma unroll
            for (int i = 0; i < 8; ++i) {
                acc[i][0] += a[i] * w4.x;
                acc[i][1] += a[i] * w4.y;
                acc[i][2] += a[i] * w4.z;
                acc[i][3] += a[i] * w4.w;
            }
        }
        __syncthreads();
    }

    float4 bv = *(const float4*)&bias[n0 + tx * 4];
#pragma unroll
    for (int i = 0; i < 8; ++i) {
        float4 o;
        o.x = acc[i][0] + bv.x;
        o.y = acc[i][1] + bv.y;
        o.z = acc[i][2] + bv.z;
        o.w = acc[i][3] + bv.w;
        *(float4*)&C[(size_t)(m0 + ty * 8 + i) * N + n0 + tx * 4] = o;
    }
}

// ---------------- persistent recurrence (tf32 mma, hi/lo weights cached) ----------------
#define RBLOCKS  128
#define RTHREADS 256

// smem layout (float offsets)
#define OFF_WG0H 0                 // [1024][8] fp32 (tf32-rounded)
#define OFF_WG1H 8192
#define OFF_WCH  16384
#define OFF_LO   24576             // u16 region: 3 x [1024][8] bf16 lo  (12288 float-slots)
#define OFF_HC   36864             // 8 warps x 3 bufs x 640
#define WSLOT    1920
#define OFF_RED  52224             // 8 x 512
#define SMEM_FLOATS 56320          // 225280 bytes

// ---- PTX helpers ----
__device__ __forceinline__ unsigned tf32_of(float f) {
    unsigned r; asm("cvt.rna.tf32.f32 %0, %1;" : "=r"(r) : "f"(f)); return r;
}
__device__ __forceinline__ void mma_tf32(float* c, const unsigned* a, const unsigned* b) {
    asm("mma.sync.aligned.m16n8k8.row.col.f32.tf32.tf32.f32 "
        "{%0,%1,%2,%3}, {%4,%5,%6,%7}, {%8,%9}, {%0,%1,%2,%3};"
        : "+f"(c[0]), "+f"(c[1]), "+f"(c[2]), "+f"(c[3])
        : "r"(a[0]), "r"(a[1]), "r"(a[2]), "r"(a[3]), "r"(b[0]), "r"(b[1]));
}
__device__ __forceinline__ void cp16(unsigned saddr, const void* g) {
    asm volatile("cp.async.cg.shared.global [%0], [%1], 16;" :: "r"(saddr), "l"(g));
}
#define CP_COMMIT() asm volatile("cp.async.commit_group;")
#define CP_WAIT(n)  asm volatile("cp.async.wait_group %0;" :: "n"(n))

__device__ __forceinline__ void grid_barrier_h(unsigned* target) {
    __syncthreads();
    if (threadIdx.x == 0) {
        __threadfence();
        atomicAdd(&g_barg[(blockIdx.x >> 4) * 64], 1u);
    }
    *target += 16;
    if (threadIdx.x < 8) {
        volatile unsigned* c = &g_barg[threadIdx.x * 64];
        while (*c < *target) { }
    }
    __threadfence();
    __syncthreads();
}

// stage one 16-col chunk of src[b][1024] for this warp: rows 0..31, cols kbase..+16
__device__ __forceinline__ void issue_chunk16(unsigned sbase, const float* __restrict__ src,
                                              int warp, int lane, int kbase, int buf) {
    unsigned dbase = sbase + (unsigned)((OFF_HC + warp * WSLOT + buf * 640 + lane * 20) * 4);
    const float* gp = src + lane * HID + kbase;
#pragma unroll
    for (int cg = 0; cg < 4; ++cg)
        cp16(dbase + cg * 16, gp + cg * 4);
}

__global__ void __launch_bounds__(RTHREADS, 1) gru_recurrent_kernel(
    const float* __restrict__ gk,
    const float* __restrict__ ck,
    float* __restrict__ out)
{
    extern __shared__ float smem[];
    const unsigned sbase = (unsigned)__cvta_generic_to_shared(smem);
    float* Wg0H = smem + OFF_WG0H;
    float* Wg1H = smem + OFF_WG1H;
    float* WcH  = smem + OFF_WCH;
    unsigned short* Wg0L = (unsigned short*)(smem + OFF_LO);
    unsigned short* Wg1L = Wg0L + 8192;
    unsigned short* WcL  = Wg0L + 16384;
    float* Red  = smem + OFF_RED;

    const int tid  = threadIdx.x;
    const int warp = tid >> 5;
    const int lane = tid & 31;
    const int g    = lane >> 2;
    const int tg   = lane & 3;

    const int p = blockIdx.x;
    const int jbaseA = p * 16;
    const int jbaseB = p * 8;
    const float* __restrict__ Ug = gk + (size_t)DIN * G2;
    const float* __restrict__ Uc = ck + (size_t)DIN * HID;

    // ---- preload + pre-convert weight slices (once) ----
    for (int idx = tid; idx < 1024 * 16; idx += RTHREADS) {
        int k = idx >> 4, j = idx & 15;
        float w = Ug[(size_t)k * G2 + jbaseA + j];
        float hi = __uint_as_float(tf32_of(w));
        __nv_bfloat16 lb = __float2bfloat16(w - hi);
        unsigned short us = *reinterpret_cast<unsigned short*>(&lb);
        if (j < 8) { Wg0H[k * 8 + j] = hi; Wg0L[k * 8 + j] = us; }
        else       { Wg1H[k * 8 + (j - 8)] = hi; Wg1L[k * 8 + (j - 8)] = us; }
    }
    for (int idx = tid; idx < 1024 * 8; idx += RTHREADS) {
        int k = idx >> 3, j = idx & 7;
        float w = Uc[(size_t)k * HID + jbaseB + j];
        float hi = __uint_as_float(tf32_of(w));
        __nv_bfloat16 lb = __float2bfloat16(w - hi);
        WcH[k * 8 + j] = hi;
        WcL[k * 8 + j] = *reinterpret_cast<unsigned short*>(&lb);
    }
    __syncthreads();

    unsigned bar_target = 0;
    const int kw = warp * 128;          // this warp's k-range base

    for (int t = 0; t < TS; ++t) {
        // =================== Phase A: gates ===================
        const int o0 = tid, o1 = tid + 256;
        const int bA0 = o0 >> 4, jA0 = o0 & 15;
        const int bA1 = o1 >> 4, jA1 = o1 & 15;
        float xg0 = __ldcg(&g_XG[((size_t)(bA0 * TS + t)) * G2 + jbaseA + jA0]);
        float xg1 = __ldcg(&g_XG[((size_t)(bA1 * TS + t)) * G2 + jbaseA + jA1]);
        float hE0 = 0.f, hE1 = 0.f;
        if (p < 64) {
            hE0 = __ldcg(&g_h[bA0 * HID + jbaseA + jA0]);
            hE1 = __ldcg(&g_h[bA1 * HID + jbaseA + jA1]);
        }

        float cA[4][4];
#pragma unroll
        for (int i = 0; i < 4; ++i)
#pragma unroll
            for (int j = 0; j < 4; ++j) cA[i][j] = 0.0f;

        issue_chunk16(sbase, g_h, warp, lane, kw + 0 * 16, 0); CP_COMMIT();
        issue_chunk16(sbase, g_h, warp, lane, kw + 1 * 16, 1); CP_COMMIT();
        issue_chunk16(sbase, g_h, warp, lane, kw + 2 * 16, 2); CP_COMMIT();

        for (int ch = 0; ch < 8; ++ch) {
            if (ch <= 5) { CP_WAIT(2); } else if (ch == 6) { CP_WAIT(1); } else { CP_WAIT(0); }
            __syncwarp();
            const float* Hb = smem + OFF_HC + warp * WSLOT + (ch % 3) * 640;
            const int kgbase = kw + ch * 16;
#pragma unroll
            for (int kk = 0; kk < 2; ++kk) {
                unsigned ahi[2][4], alo[2][4];
#pragma unroll
                for (int m = 0; m < 2; ++m)
#pragma unroll
                    for (int r = 0; r < 4; ++r) {
                        int row = m * 16 + g + (r & 1) * 8;
                        int col = kk * 8 + tg + (r >> 1) * 4;
                        float f = Hb[row * 20 + col];
                        unsigned hi = tf32_of(f);
                        ahi[m][r] = hi;
                        alo[m][r] = tf32_of(f - __uint_as_float(hi));
                    }
                const int kg = kgbase + kk * 8;
                unsigned bhi0[2], blo0[2], bhi1[2], blo1[2];
#pragma unroll
                for (int r = 0; r < 2; ++r) {
                    int krow = kg + tg + r * 4;
                    bhi0[r] = __float_as_uint(Wg0H[krow * 8 + g]);
                    blo0[r] = ((unsigned)Wg0L[krow * 8 + g]) << 16;
                    bhi1[r] = __float_as_uint(Wg1H[krow * 8 + g]);
                    blo1[r] = ((unsigned)Wg1L[krow * 8 + g]) << 16;
                }
#pragma unroll
                for (int m = 0; m < 2; ++m) {
                    mma_tf32(cA[m * 2 + 0], ahi[m], bhi0);
                    mma_tf32(cA[m * 2 + 0], ahi[m], blo0);
                    mma_tf32(cA[m * 2 + 0], alo[m], bhi0);
                    mma_tf32(cA[m * 2 + 1], ahi[m], bhi1);
                    mma_tf32(cA[m * 2 + 1], ahi[m], blo1);
                    mma_tf32(cA[m * 2 + 1], alo[m], bhi1);
                }
            }
            __syncwarp();
            if (ch + 3 < 8) { issue_chunk16(sbase, g_h, warp, lane, kw + (ch + 3) * 16, (ch + 3) % 3); CP_COMMIT(); }
        }
        // per-warp partials
#pragma unroll
        for (int m = 0; m < 2; ++m)
#pragma unroll
            for (int n = 0; n < 2; ++n) {
                float* dst = &Red[warp * 512 + (m * 16 + g) * 16 + n * 8 + 2 * tg];
                *(float2*)dst         = make_float2(cA[m * 2 + n][0], cA[m * 2 + n][1]);
                *(float2*)(dst + 128) = make_float2(cA[m * 2 + n][2], cA[m * 2 + n][3]);
            }
        __syncthreads();
        {
            float s0 = 0.f, s1 = 0.f;
#pragma unroll
            for (int w = 0; w < 8; ++w) { s0 += Red[w * 512 + o0]; s1 += Red[w * 512 + o1]; }
            float sg0 = 1.0f / (1.0f + expf(-(s0 + xg0)));
            float sg1 = 1.0f / (1.0f + expf(-(s1 + xg1)));
            if (p < 64) {
                __stcg(&g_rh[bA0 * HID + jbaseA + jA0], sg0 * hE0);
                __stcg(&g_rh[bA1 * HID + jbaseA + jA1], sg1 * hE1);
            } else {
                __stcg(&g_u[bA0 * HID + (jbaseA - 1024) + jA0], sg0);
                __stcg(&g_u[bA1 * HID + (jbaseA - 1024) + jA1], sg1);
            }
        }
        grid_barrier_h(&bar_target);

        // =================== Phase B: candidate + update ===================
        const int bB = tid >> 3, jB = tid & 7;
        float xc = __ldcg(&g_XC[((size_t)(bB * TS + t)) * HID + jbaseB + jB]);
        float uv = __ldcg(&g_u[bB * HID + jbaseB + jB]);
        float hv = __ldcg(&g_h[bB * HID + jbaseB + jB]);

        float cB[2][4];
#pragma unroll
        for (int i = 0; i < 2; ++i)
#pragma unroll
            for (int j = 0; j < 4; ++j) cB[i][j] = 0.0f;

        issue_chunk16(sbase, g_rh, warp, lane, kw + 0 * 16, 0); CP_COMMIT();
        issue_chunk16(sbase, g_rh, warp, lane, kw + 1 * 16, 1); CP_COMMIT();
        issue_chunk16(sbase, g_rh, warp, lane, kw + 2 * 16, 2); CP_COMMIT();

        for (int ch = 0; ch < 8; ++ch) {
            if (ch <= 5) { CP_WAIT(2); } else if (ch == 6) { CP_WAIT(1); } else { CP_WAIT(0); }
            __syncwarp();
            const float* Hb = smem + OFF_HC + warp * WSLOT + (ch % 3) * 640;
            const int kgbase = kw + ch * 16;
#pragma unroll
            for (int kk = 0; kk < 2; ++kk) {
                unsigned ahi[2][4], alo[2][4];
#pragma unroll
                for (int m = 0; m < 2; ++m)
#pragma unroll
                    for (int r = 0; r < 4; ++r) {
                        int row = m * 16 + g + (r & 1) * 8;
                        int col = kk * 8 + tg + (r >> 1) * 4;
                        float f = Hb[row * 20 + col];
                        unsigned hi = tf32_of(f);
                        ahi[m][r] = hi;
                        alo[m][r] = tf32_of(f - __uint_as_float(hi));
                    }
                const int kg = kgbase + kk * 8;
                unsigned bhi[2], blo[2];
#pragma unroll
                for (int r = 0; r < 2; ++r) {
                    int krow = kg + tg + r * 4;
                    bhi[r] = __float_as_uint(WcH[krow * 8 + g]);
                    blo[r] = ((unsigned)WcL[krow * 8 + g]) << 16;
                }
#pragma unroll
                for (int m = 0; m < 2; ++m) {
                    mma_tf32(cB[m], ahi[m], bhi);
                    mma_tf32(cB[m], ahi[m], blo);
                    mma_tf32(cB[m], alo[m], bhi);
                }
            }
            __syncwarp();
            if (ch + 3 < 8) { issue_chunk16(sbase, g_rh, warp, lane, kw + (ch + 3) * 16, (ch + 3) % 3); CP_COMMIT(); }
        }
#pragma unroll
        for (int m = 0; m < 2; ++m) {
            float* dst = &Red[warp * 256 + (m * 16 + g) * 8 + 2 * tg];
            *(float2*)dst        = make_float2(cB[m][0], cB[m][1]);
            *(float2*)(dst + 64) = make_float2(cB[m][2], cB[m][3]);
        }
        __syncthreads();
        {
            float s = 0.f;
#pragma unroll
            for (int w = 0; w < 8; ++w) s += Red[w * 256 + tid];
            float cc = tanhf(s + xc);
            float hn = uv * hv + (1.0f - uv) * cc;
            __stcg(&g_h[bB * HID + jbaseB + jB], hn);
            out[((size_t)bB * TS + t) * HID + jbaseB + jB] = hn;
        }
        grid_barrier_h(&bar_target);
    }
}

// ---------------- launch ----------------
extern "C" void kernel_launch(void* const* d_in, const int* in_sizes, int n_in,
                              void* d_out, int out_size) {
    const float* X  = (const float*)d_in[0];
    const float* gk = (const float*)d_in[1];
    const float* gb = (const float*)d_in[2];
    const float* ck = (const float*)d_in[3];
    const float* cb = (const float*)d_in[4];
    float* out = (float*)d_out;
    (void)in_sizes; (void)n_in; (void)out_size;

    void* pa = nullptr; void* pb = nullptr;
    cudaGetSymbolAddress(&pa, g_XG);
    cudaGetSymbolAddress(&pb, g_XC);
    float* xg_ptr = (float*)pa;
    float* xc_ptr = (float*)pb;

    cudaFuncSetAttribute(gru_recurrent_kernel,
                         cudaFuncAttributeMaxDynamicSharedMemorySize,
                         SMEM_FLOATS * (int)sizeof(float));

    gru_init_kernel<<<RBLOCKS, 256>>>();
    {
        dim3 grid(G2 / BN, (NB * TS) / BM);
        sgemm_bias_kernel<<<grid, 256>>>(X, gk, gb, xg_ptr, NB * TS, G2, DIN, G2);
    }
    {
        dim3 grid(HID / BN, (NB * TS) / BM);
        sgemm_bias_kernel<<<grid, 256>>>(X, ck, cb, xc_ptr, NB * TS, HID, DIN, HID);
    }
    gru_recurrent_kernel<<<RBLOCKS, RTHREADS, SMEM_FLOATS * sizeof(float)>>>(gk, ck, out);
}

// round 9
// speedup vs baseline: 1.4258x; 1.4258x over previous
#include <cuda_runtime.h>
#include <cuda_bf16.h>
#include <math.h>

#define TS   512
#define NB   32
#define DIN  512
#define HID  1024
#define G2   2048

// ---------------- global scratch ----------------
__device__ float g_XG[(size_t)TS * NB * G2];
__device__ float g_XC[(size_t)TS * NB * HID];
__device__ float g_h [NB * HID];
__device__ float g_rh[NB * HID];
__device__ float g_u [NB * HID];
__device__ unsigned int g_barg[8 * 64];

__global__ void gru_init_kernel() {
    int idx = blockIdx.x * blockDim.x + threadIdx.x;
    if (idx < NB * HID) g_h[idx] = 0.0f;
    if (idx < 8 * 64) g_barg[idx] = 0u;
}

// ---------------- precompute GEMM (unchanged) ----------------
#define BM 128
#define BN 64
#define BK 16
#define APAD 132

__global__ void __launch_bounds__(256) sgemm_bias_kernel(
    const float* __restrict__ A, const float* __restrict__ W,
    const float* __restrict__ bias, float* __restrict__ C,
    int M, int N, int K, int ldw)
{
    __shared__ float As[BK * APAD];
    __shared__ float Ws[BK * BN];

    const int tid = threadIdx.x;
    const int tx = tid & 15;
    const int ty = tid >> 4;
    const int m0 = blockIdx.y * BM;
    const int n0 = blockIdx.x * BN;

    float acc[8][4];
#pragma unroll
    for (int i = 0; i < 8; ++i)
#pragma unroll
        for (int j = 0; j < 4; ++j) acc[i][j] = 0.0f;

    for (int k0 = 0; k0 < K; k0 += BK) {
        {
            const int kq = tid & 3;
            const int mr = tid >> 2;
#pragma unroll
            for (int it = 0; it < 2; ++it) {
                int m = mr + it * 64;
                float4 v = *(const float4*)&A[(size_t)(m0 + m) * K + k0 + kq * 4];
                As[(kq * 4 + 0) * APAD + m] = v.x;
                As[(kq * 4 + 1) * APAD + m] = v.y;
                As[(kq * 4 + 2) * APAD + m] = v.z;
                As[(kq * 4 + 3) * APAD + m] = v.w;
            }
        }
        {
            const int nq = tid & 15;
            const int kr = tid >> 4;
            float4 v = *(const float4*)&W[(size_t)(k0 + kr) * ldw + n0 + nq * 4];
            *(float4*)&Ws[kr * BN + nq * 4] = v;
        }
        __syncthreads();
#pragma unroll
        for (int kk = 0; kk < BK; ++kk) {
            float4 w4 = *(const float4*)&Ws[kk * BN + tx * 4];
            float4 a0 = *(const float4*)&As[kk * APAD + ty * 8];
            float4 a1 = *(const float4*)&As[kk * APAD + ty * 8 + 4];
            float a[8];
            a[0] = a0.x; a[1] = a0.y; a[2] = a0.z; a[3] = a0.w;
            a[4] = a1.x; a[5] = a1.y; a[6] = a1.z; a[7] = a1.w;
#pragma unroll
            for (int i = 0; i < 8; ++i) {
                acc[i][0] += a[i] * w4.x;
                acc[i][1] += a[i] * w4.y;
                acc[i][2] += a[i] * w4.z;
                acc[i][3] += a[i] * w4.w;
            }
        }
        __syncthreads();
    }

    float4 bv = *(const float4*)&bias[n0 + tx * 4];
#pragma unroll
    for (int i = 0; i < 8; ++i) {
        float4 o;
        o.x = acc[i][0] + bv.x;
        o.y = acc[i][1] + bv.y;
        o.z = acc[i][2] + bv.z;
        o.w = acc[i][3] + bv.w;
        *(float4*)&C[(size_t)(m0 + ty * 8 + i) * N + n0 + tx * 4] = o;
    }
}

// ---------------- persistent recurrence (tf32 mma, round-7 staging + cached hi/lo weights) ----------------
#define RBLOCKS  128
#define RTHREADS 256
#define CK       256               // k per staged chunk
#define HSTRIDE  260               // h tile row stride (floats)
#define HCBUF    (32 * HSTRIDE)    // 8320 floats per buffer

// smem layout (float offsets)
#define OFF_WG0H 0                 // [1024][8] fp32 hi (tf32-rounded)
#define OFF_WG1H 8192              // [1024][8]
#define OFF_WCH  16384             // [1024][8]
#define OFF_LO   24576             // u16: 3 x [1024][8] bf16 lo (12288 float-slots)
#define OFF_HC   36864             // 2 x 8320
#define OFF_RED  53504             // 8 warps x 512
#define SMEM_FLOATS 57600          // 230400 bytes

// ---- PTX helpers ----
__device__ __forceinline__ unsigned tf32_of(float f) {
    unsigned r; asm("cvt.rna.tf32.f32 %0, %1;" : "=r"(r) : "f"(f)); return r;
}
__device__ __forceinline__ void mma_tf32(float* c, const unsigned* a, const unsigned* b) {
    asm("mma.sync.aligned.m16n8k8.row.col.f32.tf32.tf32.f32 "
        "{%0,%1,%2,%3}, {%4,%5,%6,%7}, {%8,%9}, {%0,%1,%2,%3};"
        : "+f"(c[0]), "+f"(c[1]), "+f"(c[2]), "+f"(c[3])
        : "r"(a[0]), "r"(a[1]), "r"(a[2]), "r"(a[3]), "r"(b[0]), "r"(b[1]));
}
__device__ __forceinline__ void cp16(unsigned saddr, const void* g) {
    asm volatile("cp.async.cg.shared.global [%0], [%1], 16;" :: "r"(saddr), "l"(g));
}
#define CP_COMMIT() asm volatile("cp.async.commit_group;")
#define CP_WAIT(n)  asm volatile("cp.async.wait_group %0;" :: "n"(n))

__device__ __forceinline__ void grid_barrier_h(unsigned* target) {
    __syncthreads();
    if (threadIdx.x == 0) {
        __threadfence();
        atomicAdd(&g_barg[(blockIdx.x >> 4) * 64], 1u);
    }
    *target += 16;
    if (threadIdx.x < 8) {
        volatile unsigned* c = &g_barg[threadIdx.x * 64];
        while (*c < *target) { }
    }
    __threadfence();
    __syncthreads();
}

// stage chunk c (32 batches x CK k) of src [b][1024] into smem buf [b][k] via cp.async.cg
__device__ __forceinline__ void issue_chunk(unsigned sbase, const float* __restrict__ src,
                                            int c, int buf) {
    const int tid = threadIdx.x;
#pragma unroll
    for (int it = 0; it < 8; ++it) {
        int u = tid + it * 256;          // 0..2047
        int b = u >> 6, kq = u & 63;
        const float* gp = src + b * HID + c * CK + kq * 4;
        unsigned sa = sbase + (unsigned)((OFF_HC + buf * HCBUF + b * HSTRIDE + kq * 4) * 4);
        cp16(sa, gp);
    }
}

// load A fragments (2 m-tiles, hi+lo) for one k8 from staged h tile
__device__ __forceinline__ void load_afrag(const float* __restrict__ Hb, int kloc,
                                           int g, int tg, unsigned ahi[2][4], unsigned alo[2][4]) {
#pragma unroll
    for (int m = 0; m < 2; ++m)
#pragma unroll
        for (int r = 0; r < 4; ++r) {
            int row = m * 16 + g + (r & 1) * 8;
            int col = kloc + tg + (r >> 1) * 4;
            float f = Hb[row * HSTRIDE + col];
            unsigned hi = tf32_of(f);
            ahi[m][r] = hi;
            alo[m][r] = tf32_of(f - __uint_as_float(hi));
        }
}

// load cached B fragment (hi fp32 + lo bf16<<16) for one k8
__device__ __forceinline__ void load_bfrag_cached(const float* __restrict__ WH,
                                                  const unsigned short* __restrict__ WL,
                                                  int kg, int g, int tg,
                                                  unsigned bhi[2], unsigned blo[2]) {
#pragma unroll
    for (int r = 0; r < 2; ++r) {
        int krow = kg + tg + r * 4;
        bhi[r] = __float_as_uint(WH[krow * 8 + g]);
        blo[r] = ((unsigned)WL[krow * 8 + g]) << 16;
    }
}

__global__ void __launch_bounds__(RTHREADS, 1) gru_recurrent_kernel(
    const float* __restrict__ gk,
    const float* __restrict__ ck,
    float* __restrict__ out)
{
    extern __shared__ float smem[];
    const unsigned sbase = (unsigned)__cvta_generic_to_shared(smem);
    float* Wg0H = smem + OFF_WG0H;
    float* Wg1H = smem + OFF_WG1H;
    float* WcH  = smem + OFF_WCH;
    unsigned short* Wg0L = (unsigned short*)(smem + OFF_LO);
    unsigned short* Wg1L = Wg0L + 8192;
    unsigned short* WcL  = Wg0L + 16384;
    float* Red  = smem + OFF_RED;

    const int tid  = threadIdx.x;
    const int warp = tid >> 5;
    const int lane = tid & 31;
    const int g    = lane >> 2;       // groupID (0..7)
    const int tg   = lane & 3;        // threadID_in_group

    const int p = blockIdx.x;
    const int jbaseA = p * 16;
    const int jbaseB = p * 8;
    const float* __restrict__ Ug = gk + (size_t)DIN * G2;
    const float* __restrict__ Uc = ck + (size_t)DIN * HID;

    // ---- preload + pre-convert weight slices (once) ----
    for (int idx = tid; idx < 1024 * 16; idx += RTHREADS) {
        int k = idx >> 4, j = idx & 15;
        float w = Ug[(size_t)k * G2 + jbaseA + j];
        float hi = __uint_as_float(tf32_of(w));
        __nv_bfloat16 lb = __float2bfloat16(w - hi);
        unsigned short us = *reinterpret_cast<unsigned short*>(&lb);
        if (j < 8) { Wg0H[k * 8 + j] = hi; Wg0L[k * 8 + j] = us; }
        else       { Wg1H[k * 8 + (j - 8)] = hi; Wg1L[k * 8 + (j - 8)] = us; }
    }
    for (int idx = tid; idx < 1024 * 8; idx += RTHREADS) {
        int k = idx >> 3, j = idx & 7;
        float w = Uc[(size_t)k * HID + jbaseB + j];
        float hi = __uint_as_float(tf32_of(w));
        __nv_bfloat16 lb = __float2bfloat16(w - hi);
        WcH[k * 8 + j] = hi;
        WcL[k * 8 + j] = *reinterpret_cast<unsigned short*>(&lb);
    }
    __syncthreads();

    unsigned bar_target = 0;

    for (int t = 0; t < TS; ++t) {
        // =================== Phase A: gates ===================
        const int o0 = tid, o1 = tid + 256;
        const int bA0 = o0 >> 4, jA0 = o0 & 15;
        const int bA1 = o1 >> 4, jA1 = o1 & 15;
        float xg0 = __ldcg(&g_XG[((size_t)(bA0 * TS + t)) * G2 + jbaseA + jA0]);
        float xg1 = __ldcg(&g_XG[((size_t)(bA1 * TS + t)) * G2 + jbaseA + jA1]);
        float hE0 = 0.f, hE1 = 0.f;
        if (p < 64) {
            hE0 = __ldcg(&g_h[bA0 * HID + jbaseA + jA0]);
            hE1 = __ldcg(&g_h[bA1 * HID + jbaseA + jA1]);
        }

        issue_chunk(sbase, g_h, 0, 0); CP_COMMIT();

        float cA[4][4];
#pragma unroll
        for (int i = 0; i < 4; ++i)
#pragma unroll
            for (int j = 0; j < 4; ++j) cA[i][j] = 0.0f;

#pragma unroll
        for (int c = 0; c < 4; ++c) {
            if (c < 3) { issue_chunk(sbase, g_h, c + 1, (c + 1) & 1); CP_COMMIT(); CP_WAIT(1); }
            else       { CP_WAIT(0); }
            __syncthreads();
            const float* Hb = smem + OFF_HC + (c & 1) * HCBUF;
#pragma unroll
            for (int ki = 0; ki < 4; ++ki) {
                const int kloc = warp * 32 + ki * 8;
                const int kg = c * CK + kloc;
                unsigned ahi[2][4], alo[2][4];
                load_afrag(Hb, kloc, g, tg, ahi, alo);
                unsigned bhi0[2], blo0[2], bhi1[2], blo1[2];
                load_bfrag_cached(Wg0H, Wg0L, kg, g, tg, bhi0, blo0);
                load_bfrag_cached(Wg1H, Wg1L, kg, g, tg, bhi1, blo1);
#pragma unroll
                for (int m = 0; m < 2; ++m) {
                    mma_tf32(cA[m * 2 + 0], ahi[m], bhi0);
                    mma_tf32(cA[m * 2 + 0], ahi[m], blo0);
                    mma_tf32(cA[m * 2 + 0], alo[m], bhi0);
                    mma_tf32(cA[m * 2 + 1], ahi[m], bhi1);
                    mma_tf32(cA[m * 2 + 1], ahi[m], blo1);
                    mma_tf32(cA[m * 2 + 1], alo[m], bhi1);
                }
            }
            __syncthreads();
        }
        // per-warp partials
#pragma unroll
        for (int m = 0; m < 2; ++m)
#pragma unroll
            for (int n = 0; n < 2; ++n) {
                float* dst = &Red[warp * 512 + (m * 16 + g) * 16 + n * 8 + 2 * tg];
                *(float2*)dst         = make_float2(cA[m * 2 + n][0], cA[m * 2 + n][1]);
                *(float2*)(dst + 128) = make_float2(cA[m * 2 + n][2], cA[m * 2 + n][3]);
            }
        __syncthreads();
        {
            float s0 = 0.f, s1 = 0.f;
#pragma unroll
            for (int w = 0; w < 8; ++w) { s0 += Red[w * 512 + o0]; s1 += Red[w * 512 + o1]; }
            float sg0 = 1.0f / (1.0f + expf(-(s0 + xg0)));
            float sg1 = 1.0f / (1.0f + expf(-(s1 + xg1)));
            if (p < 64) {
                __stcg(&g_rh[bA0 * HID + jbaseA + jA0], sg0 * hE0);
                __stcg(&g_rh[bA1 * HID + jbaseA + jA1], sg1 * hE1);
            } else {
                __stcg(&g_u[bA0 * HID + (jbaseA - 1024) + jA0], sg0);
                __stcg(&g_u[bA1 * HID + (jbaseA - 1024) + jA1], sg1);
            }
        }
        grid_barrier_h(&bar_target);

        // =================== Phase B: candidate + update ===================
        const int bB = tid >> 3, jB = tid & 7;
        float xc = __ldcg(&g_XC[((size_t)(bB * TS + t)) * HID + jbaseB + jB]);
        float uv = __ldcg(&g_u[bB * HID + jbaseB + jB]);
        float hv = __ldcg(&g_h[bB * HID + jbaseB + jB]);

        issue_chunk(sbase, g_rh, 0, 0); CP_COMMIT();

        float cB[2][4];
#pragma unroll
        for (int i = 0; i < 2; ++i)
#pragma unroll
            for (int j = 0; j < 4; ++j) cB[i][j] = 0.0f;

#pragma unroll
        for (int c = 0; c < 4; ++c) {
            if (c < 3) { issue_chunk(sbase, g_rh, c + 1, (c + 1) & 1); CP_COMMIT(); CP_WAIT(1); }
            else       { CP_WAIT(0); }
            __syncthreads();
            const float* Hb = smem + OFF_HC + (c & 1) * HCBUF;
#pragma unroll
            for (int ki = 0; ki < 4; ++ki) {
                const int kloc = warp * 32 + ki * 8;
                const int kg = c * CK + kloc;
                unsigned ahi[2][4], alo[2][4];
                load_afrag(Hb, kloc, g, tg, ahi, alo);
                unsigned bhi[2], blo[2];
                load_bfrag_cached(WcH, WcL, kg, g, tg, bhi, blo);
#pragma unroll
                for (int m = 0; m < 2; ++m) {
                    mma_tf32(cB[m], ahi[m], bhi);
                    mma_tf32(cB[m], ahi[m], blo);
                    mma_tf32(cB[m], alo[m], bhi);
                }
            }
            __syncthreads();
        }
#pragma unroll
        for (int m = 0; m < 2; ++m) {
            float* dst = &Red[warp * 256 + (m * 16 + g) * 8 + 2 * tg];
            *(float2*)dst        = make_float2(cB[m][0], cB[m][1]);
            *(float2*)(dst + 64) = make_float2(cB[m][2], cB[m][3]);
        }
        __syncthreads();
        {
            float s = 0.f;
#pragma unroll
            for (int w = 0; w < 8; ++w) s += Red[w * 256 + tid];
            float cc = tanhf(s + xc);
            float hn = uv * hv + (1.0f - uv) * cc;
            __stcg(&g_h[bB * HID + jbaseB + jB], hn);
            out[((size_t)bB * TS + t) * HID + jbaseB + jB] = hn;
        }
        grid_barrier_h(&bar_target);
    }
}

// ---------------- launch ----------------
extern "C" void kernel_launch(void* const* d_in, const int* in_sizes, int n_in,
                              void* d_out, int out_size) {
    const float* X  = (const float*)d_in[0];
    const float* gk = (const float*)d_in[1];
    const float* gb = (const float*)d_in[2];
    const float* ck = (const float*)d_in[3];
    const float* cb = (const float*)d_in[4];
    float* out = (float*)d_out;
    (void)in_sizes; (void)n_in; (void)out_size;

    void* pa = nullptr; void* pb = nullptr;
    cudaGetSymbolAddress(&pa, g_XG);
    cudaGetSymbolAddress(&pb, g_XC);
    float* xg_ptr = (float*)pa;
    float* xc_ptr = (float*)pb;

    cudaFuncSetAttribute(gru_recurrent_kernel,
                         cudaFuncAttributeMaxDynamicSharedMemorySize,
                         SMEM_FLOATS * (int)sizeof(float));

    gru_init_kernel<<<RBLOCKS, 256>>>();
    {
        dim3 grid(G2 / BN, (NB * TS) / BM);
        sgemm_bias_kernel<<<grid, 256>>>(X, gk, gb, xg_ptr, NB * TS, G2, DIN, G2);
    }
    {
        dim3 grid(HID / BN, (NB * TS) / BM);
        sgemm_bias_kernel<<<grid, 256>>>(X, ck, cb, xc_ptr, NB * TS, HID, DIN, HID);
    }
    gru_recurrent_kernel<<<RBLOCKS, RTHREADS, SMEM_FLOATS * sizeof(float)>>>(gk, ck, out);
}

// round 11
// speedup vs baseline: 1.8517x; 1.2987x over previous
#include <cuda_runtime.h>
#include <cuda_bf16.h>
#include <math.h>

#define TS   512
#define NB   32
#define DIN  512
#define HID  1024
#define G2   2048

// ---------------- global scratch ----------------
__device__ float    g_XG[(size_t)TS * NB * G2];
__device__ float    g_XC[(size_t)TS * NB * HID];
__device__ unsigned g_h [NB * HID];      // packed bf16 hi|lo<<16
__device__ unsigned g_rh[NB * HID];      // packed
__device__ float    g_u [NB * HID];
__device__ unsigned g_barg[8 * 64];

__global__ void gru_init_kernel() {
    int idx = blockIdx.x * blockDim.x + threadIdx.x;
    if (idx < NB * HID) g_h[idx] = 0u;
    if (idx < 8 * 64) g_barg[idx] = 0u;
}

// ---------------- pack/unpack helpers ----------------
__device__ __forceinline__ unsigned packhl(float v) {
    __nv_bfloat16 hb = __float2bfloat16(v);
    unsigned short hu = *reinterpret_cast<unsigned short*>(&hb);
    float hf = __uint_as_float((unsigned)hu << 16);
    __nv_bfloat16 lb = __float2bfloat16(v - hf);
    unsigned short lu = *reinterpret_cast<unsigned short*>(&lb);
    return (unsigned)hu | ((unsigned)lu << 16);
}
__device__ __forceinline__ float unpackhl(unsigned x) {
    return __uint_as_float(x << 16) + __uint_as_float(x & 0xFFFF0000u);
}

// ---------------- precompute GEMM (unchanged) ----------------
#define BM 128
#define BN 64
#define BK 16
#define APAD 132

__global__ void __launch_bounds__(256) sgemm_bias_kernel(
    const float* __restrict__ A, const float* __restrict__ W,
    const float* __restrict__ bias, float* __restrict__ C,
    int M, int N, int K, int ldw)
{
    __shared__ float As[BK * APAD];
    __shared__ float Ws[BK * BN];

    const int tid = threadIdx.x;
    const int tx = tid & 15;
    const int ty = tid >> 4;
    const int m0 = blockIdx.y * BM;
    const int n0 = blockIdx.x * BN;

    float acc[8][4];
#pragma unroll
    for (int i = 0; i < 8; ++i)
#pragma unroll
        for (int j = 0; j < 4; ++j) acc[i][j] = 0.0f;

    for (int k0 = 0; k0 < K; k0 += BK) {
        {
            const int kq = tid & 3;
            const int mr = tid >> 2;
#pragma unroll
            for (int it = 0; it < 2; ++it) {
                int m = mr + it * 64;
                float4 v = *(const float4*)&A[(size_t)(m0 + m) * K + k0 + kq * 4];
                As[(kq * 4 + 0) * APAD + m] = v.x;
                As[(kq * 4 + 1) * APAD + m] = v.y;
                As[(kq * 4 + 2) * APAD + m] = v.z;
                As[(kq * 4 + 3) * APAD + m] = v.w;
            }
        }
        {
            const int nq = tid & 15;
            const int kr = tid >> 4;
            float4 v = *(const float4*)&W[(size_t)(k0 + kr) * ldw + n0 + nq * 4];
            *(float4*)&Ws[kr * BN + nq * 4] = v;
        }
        __syncthreads();
#pragma unroll
        for (int kk = 0; kk < BK; ++kk) {
            float4 w4 = *(const float4*)&Ws[kk * BN + tx * 4];
            float4 a0 = *(const float4*)&As[kk * APAD + ty * 8];
            float4 a1 = *(const float4*)&As[kk * APAD + ty * 8 + 4];
            float a[8];
            a[0] = a0.x; a[1] = a0.y; a[2] = a0.z; a[3] = a0.w;
            a[4] = a1.x; a[5] = a1.y; a[6] = a1.z; a[7] = a1.w;
#pragma unroll
            for (int i = 0; i < 8; ++i) {
                acc[i][0] += a[i] * w4.x;
                acc[i][1] += a[i] * w4.y;
                acc[i][2] += a[i] * w4.z;
                acc[i][3] += a[i] * w4.w;
            }
        }
        __syncthreads();
    }

    float4 bv = *(const float4*)&bias[n0 + tx * 4];
#pragma unroll
    for (int i = 0; i < 8; ++i) {
        float4 o;
        o.x = acc[i][0] + bv.x;
        o.y = acc[i][1] + bv.y;
        o.z = acc[i][2] + bv.z;
        o.w = acc[i][3] + bv.w;
        *(float4*)&C[(size_t)(m0 + ty * 8 + i) * N + n0 + tx * 4] = o;
    }
}

// ---------------- persistent recurrence (bf16 2-pass mma, packed state) ----------------
#define RBLOCKS  128
#define RTHREADS 256
#define CK       256                 // orig k per staged chunk
#define HSTRIDE  264                 // u32 stride per batch row (256 + 8 pad; 264%32==8)
#define HCBUF    (32 * HSTRIDE)      // 8448 u32 per buffer
#define WSTRIDE  1032                // u32 stride per weight j-row (1024 + 8; %32==8)

// smem layout (u32 offsets)
#define OFF_WG   0                   // [16 j][1032 k] packed
#define OFF_WC   16512               // [8 j][1032 k]
#define OFF_HC   24768               // 2 x 8448
#define OFF_RED  41664               // 8 warps x 512 fp32
#define SMEM_U32 45760               // 183040 bytes

__device__ __forceinline__ void mma_bf16(float* c, unsigned a0, unsigned a1,
                                         unsigned a2, unsigned a3,
                                         unsigned b0, unsigned b1) {
    asm("mma.sync.aligned.m16n8k16.row.col.f32.bf16.bf16.f32 "
        "{%0,%1,%2,%3}, {%4,%5,%6,%7}, {%8,%9}, {%0,%1,%2,%3};"
        : "+f"(c[0]), "+f"(c[1]), "+f"(c[2]), "+f"(c[3])
        : "r"(a0), "r"(a1), "r"(a2), "r"(a3), "r"(b0), "r"(b1));
}
__device__ __forceinline__ void cp16(unsigned saddr, const void* g) {
    asm volatile("cp.async.cg.shared.global [%0], [%1], 16;" :: "r"(saddr), "l"(g));
}
#define CP_COMMIT() asm volatile("cp.async.commit_group;")
#define CP_WAIT(n)  asm volatile("cp.async.wait_group %0;" :: "n"(n))

__device__ __forceinline__ void grid_barrier_h(unsigned* target) {
    __syncthreads();
    if (threadIdx.x == 0) {
        __threadfence();
        atomicAdd(&g_barg[(blockIdx.x >> 4) * 64], 1u);
    }
    *target += 16;
    if (threadIdx.x < 8) {
        volatile unsigned* c = &g_barg[threadIdx.x * 64];
        while (*c < *target) { }
    }
    __threadfence();
    __syncthreads();
}

// stage chunk c (32 rows x CK u32) of packed src [b][1024] into smem buf
__device__ __forceinline__ void issue_chunk(unsigned sbase, const unsigned* __restrict__ src,
                                            int c, int buf) {
    const int tid = threadIdx.x;
#pragma unroll
    for (int it = 0; it < 8; ++it) {
        int u = tid + it * 256;          // 0..2047
        int b = u >> 6, q = u & 63;
        const unsigned* gp = src + b * HID + c * CK + q * 4;
        unsigned sa = sbase + (unsigned)((OFF_HC + buf * HCBUF + b * HSTRIDE + q * 4) * 4);
        cp16(sa, gp);
    }
}

__global__ void __launch_bounds__(RTHREADS, 1) gru_recurrent_kernel(
    const float* __restrict__ gk,
    const float* __restrict__ ck,
    float* __restrict__ out)
{
    extern __shared__ unsigned smem[];
    const unsigned sbase = (unsigned)__cvta_generic_to_shared(smem);
    unsigned* WgS = smem + OFF_WG;
    unsigned* WcS = smem + OFF_WC;
    float* Red = (float*)(smem + OFF_RED);

    const int tid  = threadIdx.x;
    const int warp = tid >> 5;
    const int lane = tid & 31;
    const int g    = lane >> 2;       // groupID (0..7)
    const int tg   = lane & 3;        // threadID_in_group

    const int p = blockIdx.x;
    const int jbaseA = p * 16;
    const int jbaseB = p * 8;
    const float* __restrict__ Ug = gk + (size_t)DIN * G2;
    const float* __restrict__ Uc = ck + (size_t)DIN * HID;

    // ---- preload + pack weight slices (once), transposed [j][k] ----
    for (int idx = tid; idx < 1024 * 16; idx += RTHREADS) {
        int k = idx >> 4, j = idx & 15;
        WgS[j * WSTRIDE + k] = packhl(Ug[(size_t)k * G2 + jbaseA + j]);
    }
    for (int idx = tid; idx < 1024 * 8; idx += RTHREADS) {
        int k = idx >> 3, j = idx & 7;
        WcS[j * WSTRIDE + k] = packhl(Uc[(size_t)k * HID + jbaseB + j]);
    }
    __syncthreads();

    unsigned bar_target = 0;

    for (int t = 0; t < TS; ++t) {
        // =================== Phase A: gates ===================
        const int o0 = tid, o1 = tid + 256;
        const int bA0 = o0 >> 4, jA0 = o0 & 15;
        const int bA1 = o1 >> 4, jA1 = o1 & 15;
        float xg0 = __ldcg(&g_XG[((size_t)(bA0 * TS + t)) * G2 + jbaseA + jA0]);
        float xg1 = __ldcg(&g_XG[((size_t)(bA1 * TS + t)) * G2 + jbaseA + jA1]);
        unsigned hE0p = 0u, hE1p = 0u;
        if (p < 64) {
            hE0p = __ldcg(&g_h[bA0 * HID + jbaseA + jA0]);
            hE1p = __ldcg(&g_h[bA1 * HID + jbaseA + jA1]);
        }

        issue_chunk(sbase, g_h, 0, 0); CP_COMMIT();

        float cA[4][4];
#pragma unroll
        for (int i = 0; i < 4; ++i)
#pragma unroll
            for (int j = 0; j < 4; ++j) cA[i][j] = 0.0f;

#pragma unroll
        for (int c = 0; c < 4; ++c) {
            if (c < 3) { issue_chunk(sbase, g_h, c + 1, (c + 1) & 1); CP_COMMIT(); CP_WAIT(1); }
            else       { CP_WAIT(0); }
            __syncthreads();
            const unsigned* Hb = smem + OFF_HC + (c & 1) * HCBUF;
#pragma unroll
            for (int ki = 0; ki < 4; ++ki) {
                const int kl = warp * 32 + ki * 8;   // orig k within chunk
                const int kg = c * CK + kl;          // orig k global
                // A fragments: packed u32 pairs via LDS.64
                uint2 va0 = *(const uint2*)&Hb[(g)      * HSTRIDE + kl + 2 * tg];
                uint2 va1 = *(const uint2*)&Hb[(g + 8)  * HSTRIDE + kl + 2 * tg];
                uint2 va2 = *(const uint2*)&Hb[(g + 16) * HSTRIDE + kl + 2 * tg];
                uint2 va3 = *(const uint2*)&Hb[(g + 24) * HSTRIDE + kl + 2 * tg];
                // W fragments
                uint2 w0 = *(const uint2*)&WgS[(g)     * WSTRIDE + kg + 2 * tg];
                uint2 w1 = *(const uint2*)&WgS[(g + 8) * WSTRIDE + kg + 2 * tg];
                unsigned n0p1b0 = __byte_perm(w0.x, 0, 0x1010);
                unsigned n0p1b1 = __byte_perm(w0.y, 0, 0x1010);
                unsigned n0p2b0 = w0.x >> 16, n0p2b1 = w0.y >> 16;
                unsigned n1p1b0 = __byte_perm(w1.x, 0, 0x1010);
                unsigned n1p1b1 = __byte_perm(w1.y, 0, 0x1010);
                unsigned n1p2b0 = w1.x >> 16, n1p2b1 = w1.y >> 16;
                // m-tile 0
                mma_bf16(cA[0], va0.x, va1.x, va0.y, va1.y, n0p1b0, n0p1b1);
                mma_bf16(cA[0], va0.x, va1.x, va0.y, va1.y, n0p2b0, n0p2b1);
                mma_bf16(cA[1], va0.x, va1.x, va0.y, va1.y, n1p1b0, n1p1b1);
                mma_bf16(cA[1], va0.x, va1.x, va0.y, va1.y, n1p2b0, n1p2b1);
                // m-tile 1
                mma_bf16(cA[2], va2.x, va3.x, va2.y, va3.y, n0p1b0, n0p1b1);
                mma_bf16(cA[2], va2.x, va3.x, va2.y, va3.y, n0p2b0, n0p2b1);
                mma_bf16(cA[3], va2.x, va3.x, va2.y, va3.y, n1p1b0, n1p1b1);
                mma_bf16(cA[3], va2.x, va3.x, va2.y, va3.y, n1p2b0, n1p2b1);
            }
            __syncthreads();
        }
        // per-warp partials (same C-frag map as m16n8k8)
#pragma unroll
        for (int m = 0; m < 2; ++m)
#pragma unroll
            for (int n = 0; n < 2; ++n) {
                float* dst = &Red[warp * 512 + (m * 16 + g) * 16 + n * 8 + 2 * tg];
                *(float2*)dst         = make_float2(cA[m * 2 + n][0], cA[m * 2 + n][1]);
                *(float2*)(dst + 128) = make_float2(cA[m * 2 + n][2], cA[m * 2 + n][3]);
            }
        __syncthreads();
        {
            float s0 = 0.f, s1 = 0.f;
#pragma unroll
            for (int w = 0; w < 8; ++w) { s0 += Red[w * 512 + o0]; s1 += Red[w * 512 + o1]; }
            float sg0 = 1.0f / (1.0f + expf(-(s0 + xg0)));
            float sg1 = 1.0f / (1.0f + expf(-(s1 + xg1)));
            if (p < 64) {
                __stcg(&g_rh[bA0 * HID + jbaseA + jA0], packhl(sg0 * unpackhl(hE0p)));
                __stcg(&g_rh[bA1 * HID + jbaseA + jA1], packhl(sg1 * unpackhl(hE1p)));
            } else {
                __stcg(&g_u[bA0 * HID + (jbaseA - 1024) + jA0], sg0);
                __stcg(&g_u[bA1 * HID + (jbaseA - 1024) + jA1], sg1);
            }
        }
        grid_barrier_h(&bar_target);

        // =================== Phase B: candidate + update ===================
        const int bB = tid >> 3, jB = tid & 7;
        float xc = __ldcg(&g_XC[((size_t)(bB * TS + t)) * HID + jbaseB + jB]);
        float uv = __ldcg(&g_u[bB * HID + jbaseB + jB]);
        unsigned hvp = __ldcg(&g_h[bB * HID + jbaseB + jB]);

        issue_chunk(sbase, g_rh, 0, 0); CP_COMMIT();

        float cB[2][4];
#pragma unroll
        for (int i = 0; i < 2; ++i)
#pragma unroll
            for (int j = 0; j < 4; ++j) cB[i][j] = 0.0f;

#pragma unroll
        for (int c = 0; c < 4; ++c) {
            if (c < 3) { issue_chunk(sbase, g_rh, c + 1, (c + 1) & 1); CP_COMMIT(); CP_WAIT(1); }
            else       { CP_WAIT(0); }
            __syncthreads();
            const unsigned* Hb = smem + OFF_HC + (c & 1) * HCBUF;
#pragma unroll
            for (int ki = 0; ki < 4; ++ki) {
                const int kl = warp * 32 + ki * 8;
                const int kg = c * CK + kl;
                uint2 va0 = *(const uint2*)&Hb[(g)      * HSTRIDE + kl + 2 * tg];
                uint2 va1 = *(const uint2*)&Hb[(g + 8)  * HSTRIDE + kl + 2 * tg];
                uint2 va2 = *(const uint2*)&Hb[(g + 16) * HSTRIDE + kl + 2 * tg];
                uint2 va3 = *(const uint2*)&Hb[(g + 24) * HSTRIDE + kl + 2 * tg];
                uint2 w0 = *(const uint2*)&WcS[(g) * WSTRIDE + kg + 2 * tg];
                unsigned p1b0 = __byte_perm(w0.x, 0, 0x1010);
                unsigned p1b1 = __byte_perm(w0.y, 0, 0x1010);
                unsigned p2b0 = w0.x >> 16, p2b1 = w0.y >> 16;
                mma_bf16(cB[0], va0.x, va1.x, va0.y, va1.y, p1b0, p1b1);
                mma_bf16(cB[0], va0.x, va1.x, va0.y, va1.y, p2b0, p2b1);
                mma_bf16(cB[1], va2.x, va3.x, va2.y, va3.y, p1b0, p1b1);
                mma_bf16(cB[1], va2.x, va3.x, va2.y, va3.y, p2b0, p2b1);
            }
            __syncthreads();
        }
#pragma unroll
        for (int m = 0; m < 2; ++m) {
            float* dst = &Red[warp * 256 + (m * 16 + g) * 8 + 2 * tg];
            *(float2*)dst        = make_float2(cB[m][0], cB[m][1]);
            *(float2*)(dst + 64) = make_float2(cB[m][2], cB[m][3]);
        }
        __syncthreads();
        {
            float s = 0.f;
#pragma unroll
            for (int w = 0; w < 8; ++w) s += Red[w * 256 + tid];
            float cc = tanhf(s + xc);
            float hv = unpackhl(hvp);
            float hn = uv * hv + (1.0f - uv) * cc;
            __stcg(&g_h[bB * HID + jbaseB + jB], packhl(hn));
            out[((size_t)bB * TS + t) * HID + jbaseB + jB] = hn;
        }
        grid_barrier_h(&bar_target);
    }
}

// ---------------- launch ----------------
extern "C" void kernel_launch(void* const* d_in, const int* in_sizes, int n_in,
                              void* d_out, int out_size) {
    const float* X  = (const float*)d_in[0];
    const float* gk = (const float*)d_in[1];
    const float* gb = (const float*)d_in[2];
    const float* ck = (const float*)d_in[3];
    const float* cb = (const float*)d_in[4];
    float* out = (float*)d_out;
    (void)in_sizes; (void)n_in; (void)out_size;

    void* pa = nullptr; void* pb = nullptr;
    cudaGetSymbolAddress(&pa, g_XG);
    cudaGetSymbolAddress(&pb, g_XC);
    float* xg_ptr = (float*)pa;
    float* xc_ptr = (float*)pb;

    cudaFuncSetAttribute(gru_recurrent_kernel,
                         cudaFuncAttributeMaxDynamicSharedMemorySize,
                         SMEM_U32 * (int)sizeof(unsigned));

    gru_init_kernel<<<RBLOCKS, 256>>>();
    {
        dim3 grid(G2 / BN, (NB * TS) / BM);
        sgemm_bias_kernel<<<grid, 256>>>(X, gk, gb, xg_ptr, NB * TS, G2, DIN, G2);
    }
    {
        dim3 grid(HID / BN, (NB * TS) / BM);
        sgemm_bias_kernel<<<grid, 256>>>(X, ck, cb, xc_ptr, NB * TS, HID, DIN, HID);
    }
    gru_recurrent_kernel<<<RBLOCKS, RTHREADS, SMEM_U32 * sizeof(unsigned)>>>(gk, ck, out);
}